// round 2
// baseline (speedup 1.0000x reference)
#include <cuda_runtime.h>
#include <cstdint>

#define HDIM 128
#define TSEQ 512
#define BATCH 128
#define GB 4
#define RSTRIDE 132   // phase-2 padded stride

typedef unsigned long long u64;

// scratch (device globals: allocation-free rule)
__device__ float g_h2[(size_t)TSEQ * BATCH * HDIM];   // [t][b][h]
__device__ float g_dold[TSEQ * BATCH];
__device__ float g_dh[TSEQ * BATCH];

__device__ __forceinline__ float sigm(float x) {
    return __fdividef(1.f, 1.f + __expf(-x));
}
__device__ __forceinline__ float tanh_fast(float x) {
    x = fminf(fmaxf(x, -15.f), 15.f);
    float e = __expf(2.f * x);
    return __fdividef(e - 1.f, e + 1.f);
}

__device__ __forceinline__ u64 ffma2(u64 a, u64 b, u64 c) {
    u64 d;
    asm("fma.rn.f32x2 %0, %1, %2, %3;" : "=l"(d) : "l"(a), "l"(b), "l"(c));
    return d;
}
__device__ __forceinline__ float2 unpack2(u64 v) {
    float2 r;
    asm("mov.b64 {%0, %1}, %2;" : "=f"(r.x), "=f"(r.y) : "l"(v));
    return r;
}

__device__ __forceinline__ void st_cluster_f32(float* p, int rank, float v) {
    uint32_t la = (uint32_t)__cvta_generic_to_shared(p);
    uint32_t ra;
    asm volatile("mapa.shared::cluster.u32 %0, %1, %2;" : "=r"(ra) : "r"(la), "r"(rank));
    asm volatile("st.shared::cluster.f32 [%0], %1;" :: "r"(ra), "f"(v) : "memory");
}
__device__ __forceinline__ void mbar_init(uint32_t a, uint32_t cnt) {
    asm volatile("mbarrier.init.shared.b64 [%0], %1;" :: "r"(a), "r"(cnt) : "memory");
}
__device__ __forceinline__ void mbar_arrive_rank(uint32_t local_addr, uint32_t rank) {
    asm volatile(
        "{\n\t.reg .b32 ra;\n\t"
        "mapa.shared::cluster.u32 ra, %0, %1;\n\t"
        "mbarrier.arrive.release.cluster.shared::cluster.b64 _, [ra];\n\t}"
        :: "r"(local_addr), "r"(rank) : "memory");
}
__device__ __forceinline__ void mbar_wait(uint32_t addr, uint32_t parity) {
    asm volatile(
        "{\n\t.reg .pred P;\n"
        "WL_%=:\n\t"
        "mbarrier.try_wait.parity.acquire.cluster.shared::cta.b64 P, [%0], %1, 0x989680;\n\t"
        "@P bra WD_%=;\n\t"
        "bra WL_%=;\n"
        "WD_%=:\n\t}"
        :: "r"(addr), "r"(parity) : "memory");
}
__device__ __forceinline__ void cluster_sync_() {
    asm volatile("barrier.cluster.arrive.aligned;" ::: "memory");
    asm volatile("barrier.cluster.wait.aligned;" ::: "memory");
}

// ---------------------------------------------------------------------------
// Phase 1: sequential 2-layer LSTM. 32 clusters x 4 CTAs, 4 batches/cluster.
// All three weight matrices live in REGISTERS (96 regs/thread):
//   layer 1: thread (j=tid>>2, q=tid&3)  -> Whh1 row j, k-quarter q  (16 f32x2)
//   layer 2: thread (vr=tid>>1, kh=tid&1)-> (Wih2|Whh2) row vr&127, k-half kh (32 f32x2)
// Partial dots reduced by shfl_xor; gates assembled in SMEM; cell update by
// tid<128; activation slices exchanged via DSMEM stores + mbarrier rounds.
// ---------------------------------------------------------------------------
__global__ void __launch_bounds__(512, 1) __cluster_dims__(4, 1, 1)
lstm_seq_kernel(const float* __restrict__ x,
                const float* __restrict__ Wih1, const float* __restrict__ Whh1,
                const float* __restrict__ bih1, const float* __restrict__ bhh1,
                const float* __restrict__ Wih2, const float* __restrict__ Whh2,
                const float* __restrict__ bih2, const float* __restrict__ bhh2)
{
    __shared__ __align__(16) float h1buf[2][GB][HDIM];
    __shared__ __align__(16) float c1buf[2][GB][HDIM];
    __shared__ __align__(16) float h2buf[2][GB][HDIM];
    __shared__ float xs[GB][TSEQ];
    __shared__ __align__(16) float gbuf[512];       // layer-1 gates [row*4+b]
    __shared__ __align__(16) float part2[256 * 4];  // layer-2 partials [vrow*4+b]
    __shared__ float bias1s[128], bias2s[128], wih1s[128];
    __shared__ __align__(8) u64 mbar[2];

    const int tid  = threadIdx.x;
    const int rank = blockIdx.x & 3;
    const int bg0  = (blockIdx.x >> 2) * GB;

    // ---- roles
    const int j1 = tid >> 2, q1 = tid & 3;          // layer 1
    const int vr = tid >> 1, kh = tid & 1;          // layer 2
    const int m2 = vr >> 7,  r2 = vr & 127;
    const int cu = tid & 31, cb = tid >> 5;         // cell (tid<128)
    const int slot = rank * 32 + cu;

    // ---- register-resident weights
    u64 w1[16], w2[32];
    {
        const int gr1 = (j1 >> 5) * 128 + rank * 32 + (j1 & 31);
        const float* src1 = Whh1 + (size_t)gr1 * 128 + q1 * 32;
        #pragma unroll
        for (int k = 0; k < 16; k++) w1[k] = *(const u64*)(src1 + 2 * k);

        const int gr2 = (r2 >> 5) * 128 + rank * 32 + (r2 & 31);
        const float* Wm = m2 ? Whh2 : Wih2;
        const float* src2 = Wm + (size_t)gr2 * 128 + kh * 64;
        #pragma unroll
        for (int k = 0; k < 32; k++) w2[k] = *(const u64*)(src2 + 2 * k);
    }

    if (tid < 128) {
        int gr = (tid >> 5) * 128 + rank * 32 + (tid & 31);
        bias1s[tid] = bih1[gr] + bhh1[gr];
        bias2s[tid] = bih2[gr] + bhh2[gr];
        wih1s[tid]  = Wih1[gr];
    }
    for (int idx = tid; idx < GB * TSEQ; idx += 512) {
        int b = idx >> 9, tt = idx & (TSEQ - 1);
        xs[b][tt] = x[(size_t)(bg0 + b) * TSEQ + tt];
    }
    for (int idx = tid; idx < 2 * GB * HDIM; idx += 512) {
        ((float*)h1buf)[idx] = 0.f;
        ((float*)c1buf)[idx] = 0.f;
        ((float*)h2buf)[idx] = 0.f;
    }
    const uint32_t mb1a = (uint32_t)__cvta_generic_to_shared(&mbar[0]);
    const uint32_t mb2a = (uint32_t)__cvta_generic_to_shared(&mbar[1]);
    if (tid == 0) { mbar_init(mb1a, 4); mbar_init(mb2a, 4); }
    __syncthreads();
    cluster_sync_();   // peers see our zeroed buffers + initialized mbarriers

    float c1s = 0.f, c2s = 0.f;
    int p = 0;
    float* g_h2p = g_h2 + (size_t)(bg0 + cb) * HDIM + slot;

    for (int t = 0; t < TSEQ; t++) {
        const int pn = p ^ 1;
        const uint32_t par = (uint32_t)(t & 1);

        // ================= layer 1 matvec: Whh1_row(j1) . h1 ================
        {
            const ulonglong2* h0 = (const ulonglong2*)(&h1buf[p][0][q1 * 32]);
            const ulonglong2* h1v = (const ulonglong2*)(&h1buf[p][1][q1 * 32]);
            const ulonglong2* h2v = (const ulonglong2*)(&h1buf[p][2][q1 * 32]);
            const ulonglong2* h3v = (const ulonglong2*)(&h1buf[p][3][q1 * 32]);
            u64 a0 = 0, a1 = 0, a2 = 0, a3 = 0;
            #pragma unroll
            for (int k = 0; k < 8; k++) {
                ulonglong2 v0 = h0[k], v1 = h1v[k], v2 = h2v[k], v3 = h3v[k];
                a0 = ffma2(w1[2 * k], v0.x, a0); a0 = ffma2(w1[2 * k + 1], v0.y, a0);
                a1 = ffma2(w1[2 * k], v1.x, a1); a1 = ffma2(w1[2 * k + 1], v1.y, a1);
                a2 = ffma2(w1[2 * k], v2.x, a2); a2 = ffma2(w1[2 * k + 1], v2.y, a2);
                a3 = ffma2(w1[2 * k], v3.x, a3); a3 = ffma2(w1[2 * k + 1], v3.y, a3);
            }
            float2 f0 = unpack2(a0), f1 = unpack2(a1), f2 = unpack2(a2), f3 = unpack2(a3);
            float s0 = f0.x + f0.y, s1 = f1.x + f1.y, s2 = f2.x + f2.y, s3 = f3.x + f3.y;
            s0 += __shfl_xor_sync(0xffffffffu, s0, 1); s0 += __shfl_xor_sync(0xffffffffu, s0, 2);
            s1 += __shfl_xor_sync(0xffffffffu, s1, 1); s1 += __shfl_xor_sync(0xffffffffu, s1, 2);
            s2 += __shfl_xor_sync(0xffffffffu, s2, 1); s2 += __shfl_xor_sync(0xffffffffu, s2, 2);
            s3 += __shfl_xor_sync(0xffffffffu, s3, 1); s3 += __shfl_xor_sync(0xffffffffu, s3, 2);
            float sv = (q1 == 0) ? s0 : (q1 == 1) ? s1 : (q1 == 2) ? s2 : s3;
            gbuf[tid] = sv;
        }
        __syncthreads();

        // ================= cell 1 (tid<128) =================
        if (tid < 128) {
            float xv = xs[cb][t];
            float gi = gbuf[(cu)      * 4 + cb] + fmaf(wih1s[cu],      xv, bias1s[cu]);
            float gf = gbuf[(32 + cu) * 4 + cb] + fmaf(wih1s[32 + cu], xv, bias1s[32 + cu]);
            float gg = gbuf[(64 + cu) * 4 + cb] + fmaf(wih1s[64 + cu], xv, bias1s[64 + cu]);
            float go = gbuf[(96 + cu) * 4 + cb] + fmaf(wih1s[96 + cu], xv, bias1s[96 + cu]);
            c1s = sigm(gf) * c1s + sigm(gi) * tanh_fast(gg);
            float h1n = sigm(go) * tanh_fast(c1s);
            #pragma unroll
            for (int r = 0; r < 4; r++) {
                st_cluster_f32(&h1buf[pn][cb][slot], r, h1n);
                st_cluster_f32(&c1buf[pn][cb][slot], r, c1s);
            }
            asm volatile("bar.sync 1, 128;" ::: "memory");
            if (tid == 0) {
                asm volatile("fence.acq_rel.cluster;" ::: "memory");
                #pragma unroll
                for (int r = 0; r < 4; r++) mbar_arrive_rank(mb1a, r);
            }
        }
        mbar_wait(mb1a, par);

        // ===== layer 2 matvec: (Wih2 row).c1  or  (Whh2 row).h2 per thread ====
        {
            const float* inb = m2 ? &h2buf[p][0][0] : &c1buf[pn][0][0];
            const ulonglong2* h0 = (const ulonglong2*)(inb + 0 * HDIM + kh * 64);
            const ulonglong2* h1v = (const ulonglong2*)(inb + 1 * HDIM + kh * 64);
            const ulonglong2* h2v = (const ulonglong2*)(inb + 2 * HDIM + kh * 64);
            const ulonglong2* h3v = (const ulonglong2*)(inb + 3 * HDIM + kh * 64);
            u64 a0 = 0, a1 = 0, a2 = 0, a3 = 0;
            #pragma unroll
            for (int k = 0; k < 16; k++) {
                ulonglong2 v0 = h0[k], v1 = h1v[k], v2 = h2v[k], v3 = h3v[k];
                a0 = ffma2(w2[2 * k], v0.x, a0); a0 = ffma2(w2[2 * k + 1], v0.y, a0);
                a1 = ffma2(w2[2 * k], v1.x, a1); a1 = ffma2(w2[2 * k + 1], v1.y, a1);
                a2 = ffma2(w2[2 * k], v2.x, a2); a2 = ffma2(w2[2 * k + 1], v2.y, a2);
                a3 = ffma2(w2[2 * k], v3.x, a3); a3 = ffma2(w2[2 * k + 1], v3.y, a3);
            }
            float2 f0 = unpack2(a0), f1 = unpack2(a1), f2 = unpack2(a2), f3 = unpack2(a3);
            float s0 = f0.x + f0.y, s1 = f1.x + f1.y, s2 = f2.x + f2.y, s3 = f3.x + f3.y;
            s0 += __shfl_xor_sync(0xffffffffu, s0, 1);
            s1 += __shfl_xor_sync(0xffffffffu, s1, 1);
            s2 += __shfl_xor_sync(0xffffffffu, s2, 1);
            s3 += __shfl_xor_sync(0xffffffffu, s3, 1);
            if (kh == 0)
                *(float4*)&part2[vr * 4] = make_float4(s0, s1, s2, s3);
        }
        __syncthreads();

        // ================= cell 2 (tid<128) =================
        if (tid < 128) {
            float gi = part2[(cu)       * 4 + cb] + part2[(128 + cu) * 4 + cb] + bias2s[cu];
            float gf = part2[(32 + cu)  * 4 + cb] + part2[(160 + cu) * 4 + cb] + bias2s[32 + cu];
            float gg = part2[(64 + cu)  * 4 + cb] + part2[(192 + cu) * 4 + cb] + bias2s[64 + cu];
            float go = part2[(96 + cu)  * 4 + cb] + part2[(224 + cu) * 4 + cb] + bias2s[96 + cu];
            c2s = sigm(gf) * c2s + sigm(gi) * tanh_fast(gg);
            float h2n = sigm(go) * tanh_fast(c2s);
            #pragma unroll
            for (int r = 0; r < 4; r++)
                st_cluster_f32(&h2buf[pn][cb][slot], r, h2n);
            g_h2p[(size_t)t * (BATCH * HDIM)] = h2n;
            asm volatile("bar.sync 1, 128;" ::: "memory");
            if (tid == 0) {
                asm volatile("fence.acq_rel.cluster;" ::: "memory");
                #pragma unroll
                for (int r = 0; r < 4; r++) mbar_arrive_rank(mb2a, r);
            }
        }
        mbar_wait(mb2a, par);
        p ^= 1;
    }
}

// ---------------------------------------------------------------------------
// Phase 2a: d_old[t,b] = h2[t,b].wt_old ; d_h[t,b] = h2[t,b].wt_h
// ---------------------------------------------------------------------------
__global__ void dots_kernel(const float* __restrict__ w_t)
{
    int gid  = blockIdx.x * blockDim.x + threadIdx.x;
    int gw   = gid >> 5;
    int lane = gid & 31;
    if (gw >= TSEQ * BATCH) return;
    float4 h = *(const float4*)(g_h2 + (size_t)gw * HDIM + lane * 4);
    float4 a = *(const float4*)(w_t + lane * 4);
    float4 o = *(const float4*)(w_t + HDIM + lane * 4);
    float dh   = h.x * a.x + h.y * a.y + h.z * a.z + h.w * a.w;
    float dold = h.x * o.x + h.y * o.y + h.z * o.z + h.w * o.w;
    #pragma unroll
    for (int off = 16; off; off >>= 1) {
        dh   += __shfl_down_sync(0xffffffffu, dh, off);
        dold += __shfl_down_sync(0xffffffffu, dold, off);
    }
    if (lane == 0) { g_dh[gw] = dh; g_dold[gw] = dold; }
}

// ---------------------------------------------------------------------------
// Phase 2b: per t: global softmax over (slot,batch), attention gather, FC.
// ---------------------------------------------------------------------------
__global__ void __launch_bounds__(256, 1)
attn_fc_kernel(const float* __restrict__ fcW, const float* __restrict__ fcb,
               float* __restrict__ out)
{
    extern __shared__ float sm[];
    float* sFcT = sm;                       // [128][132]
    float* sPre = sFcT + 128 * RSTRIDE;     // [128][132]
    float* sE   = sPre + 128 * RSTRIDE;     // [33][128]
    float* sHd  = sE + 33 * 128;            // [128]
    float* sFcb = sHd + 128;                // [128]
    float* sRed = sFcb + 128;               // [256]

    const int t    = blockIdx.x;
    const int tid  = threadIdx.x;
    const int lane = tid & 31;
    const int warp = tid >> 5;

    for (int idx = tid; idx < 128 * 128; idx += 256) {
        int c = idx >> 7, h = idx & 127;
        sFcT[h * RSTRIDE + c] = fcW[idx];
    }
    if (tid < 128) {
        sFcb[tid] = fcb[tid];
        sHd[tid]  = g_dh[t * BATCH + tid];
    }
    __syncthreads();

    const int s_min = (t < 32) ? (32 - t) : 0;
    const int nsc   = (33 - s_min) * 128;
    float lmax = -1e30f;
    for (int n = tid; n < nsc; n += 256) {
        int s = s_min + (n >> 7), b = n & 127;
        int idx = t - 33 + s;
        float sc = sHd[b] + (idx >= 0 ? g_dold[idx * BATCH + b] : 0.f);
        sE[s * 128 + b] = sc;
        lmax = fmaxf(lmax, sc);
    }
    sRed[tid] = lmax; __syncthreads();
    for (int off = 128; off; off >>= 1) {
        if (tid < off) sRed[tid] = fmaxf(sRed[tid], sRed[tid + off]);
        __syncthreads();
    }
    float mx = sRed[0];
    __syncthreads();
    float lsum = 0.f;
    for (int n = tid; n < nsc; n += 256) {
        int s = s_min + (n >> 7), b = n & 127;
        float e = __expf(sE[s * 128 + b] - mx);
        sE[s * 128 + b] = e;
        lsum += e;
    }
    sRed[tid] = lsum; __syncthreads();
    for (int off = 128; off; off >>= 1) {
        if (tid < off) sRed[tid] += sRed[tid + off];
        __syncthreads();
    }
    float inv = __fdividef(1.f, sRed[0]);
    __syncthreads();

    const int s_att = (t < 33) ? (33 - t) : 0;
    for (int b = warp; b < 128; b += 8) {
        float4 acc; acc.x = acc.y = acc.z = acc.w = 0.f;
        for (int s = s_att; s < 33; s++) {
            float w  = sE[s * 128 + b];
            float4 v = *(const float4*)(g_h2 + (size_t)(t - 33 + s) * (BATCH * HDIM)
                                              + (size_t)b * HDIM + lane * 4);
            acc.x += w * v.x; acc.y += w * v.y; acc.z += w * v.z; acc.w += w * v.w;
        }
        float4 hc = *(const float4*)(g_h2 + (size_t)t * (BATCH * HDIM)
                                           + (size_t)b * HDIM + lane * 4);
        float4 pre;
        pre.x = hc.x + inv * acc.x; pre.y = hc.y + inv * acc.y;
        pre.z = hc.z + inv * acc.z; pre.w = hc.w + inv * acc.w;
        *(float4*)(sPre + b * RSTRIDE + lane * 4) = pre;
    }
    __syncthreads();

    const int c0 = lane * 4;
    float4 bias = *(const float4*)(sFcb + c0);
    for (int r = 0; r < 4; r++) {
        int b0 = (warp + 8 * r) * 4;
        float4 a0, a1, a2, a3;
        a0.x=a0.y=a0.z=a0.w=0.f; a1=a0; a2=a0; a3=a0;
        const float4* p0 = (const float4*)(sPre + (size_t)(b0 + 0) * RSTRIDE);
        const float4* p1 = (const float4*)(sPre + (size_t)(b0 + 1) * RSTRIDE);
        const float4* p2 = (const float4*)(sPre + (size_t)(b0 + 2) * RSTRIDE);
        const float4* p3 = (const float4*)(sPre + (size_t)(b0 + 3) * RSTRIDE);
        #pragma unroll
        for (int h4 = 0; h4 < 32; h4++) {
            float4 q0 = p0[h4], q1 = p1[h4], q2 = p2[h4], q3 = p3[h4];
            #pragma unroll
            for (int hh = 0; hh < 4; hh++) {
                float4 w = *(const float4*)(sFcT + (h4 * 4 + hh) * RSTRIDE + c0);
                float v0 = (&q0.x)[hh], v1 = (&q1.x)[hh], v2 = (&q2.x)[hh], v3 = (&q3.x)[hh];
                a0.x += v0 * w.x; a0.y += v0 * w.y; a0.z += v0 * w.z; a0.w += v0 * w.w;
                a1.x += v1 * w.x; a1.y += v1 * w.y; a1.z += v1 * w.z; a1.w += v1 * w.w;
                a2.x += v2 * w.x; a2.y += v2 * w.y; a2.z += v2 * w.z; a2.w += v2 * w.w;
                a3.x += v3 * w.x; a3.y += v3 * w.y; a3.z += v3 * w.z; a3.w += v3 * w.w;
            }
        }
        a0.x += bias.x; a0.y += bias.y; a0.z += bias.z; a0.w += bias.w;
        a1.x += bias.x; a1.y += bias.y; a1.z += bias.z; a1.w += bias.w;
        a2.x += bias.x; a2.y += bias.y; a2.z += bias.z; a2.w += bias.w;
        a3.x += bias.x; a3.y += bias.y; a3.z += bias.z; a3.w += bias.w;
        size_t obase = (size_t)t * 128 + c0;
        *(float4*)(out + (size_t)(b0 + 0) * (TSEQ * 128) + obase) = a0;
        *(float4*)(out + (size_t)(b0 + 1) * (TSEQ * 128) + obase) = a1;
        *(float4*)(out + (size_t)(b0 + 2) * (TSEQ * 128) + obase) = a2;
        *(float4*)(out + (size_t)(b0 + 3) * (TSEQ * 128) + obase) = a3;
    }
}

// ---------------------------------------------------------------------------
extern "C" void kernel_launch(void* const* d_in, const int* in_sizes, int n_in,
                              void* d_out, int out_size)
{
    const float* x    = (const float*)d_in[0];
    const float* Wih1 = (const float*)d_in[1];
    const float* Whh1 = (const float*)d_in[2];
    const float* bih1 = (const float*)d_in[3];
    const float* bhh1 = (const float*)d_in[4];
    const float* Wih2 = (const float*)d_in[5];
    const float* Whh2 = (const float*)d_in[6];
    const float* bih2 = (const float*)d_in[7];
    const float* bhh2 = (const float*)d_in[8];
    const float* w_t  = (const float*)d_in[9];
    const float* fcW  = (const float*)d_in[10];
    const float* fcb  = (const float*)d_in[11];
    float* out = (float*)d_out;

    const int smem3 = (2 * 128 * RSTRIDE + 33 * 128 + 128 + 128 + 256) * (int)sizeof(float);
    cudaFuncSetAttribute(attn_fc_kernel, cudaFuncAttributeMaxDynamicSharedMemorySize, smem3);

    lstm_seq_kernel<<<128, 512>>>(x, Wih1, Whh1, bih1, bhh1,
                                  Wih2, Whh2, bih2, bhh2);
    dots_kernel<<<(TSEQ * BATCH * 32) / 256, 256>>>(w_t);
    attn_fc_kernel<<<TSEQ, 256, smem3>>>(fcW, fcb, out);
}

// round 3
// speedup vs baseline: 1.9608x; 1.9608x over previous
#include <cuda_runtime.h>
#include <cstdint>

#define HDIM 128
#define TSEQ 512
#define BATCH 128
#define GB 4
#define RSTRIDE 132
#define W1STRIDE 132

typedef unsigned long long u64;

__device__ float g_h2[(size_t)TSEQ * BATCH * HDIM];   // [t][b][h]
__device__ float g_dold[TSEQ * BATCH];
__device__ float g_dh[TSEQ * BATCH];

__device__ __forceinline__ float sigm(float x) {
    return __fdividef(1.f, 1.f + __expf(-x));
}
__device__ __forceinline__ float tanh_fast(float x) {
    x = fminf(fmaxf(x, -15.f), 15.f);
    float e = __expf(2.f * x);
    return __fdividef(e - 1.f, e + 1.f);
}
__device__ __forceinline__ u64 ffma2(u64 a, u64 b, u64 c) {
    u64 d;
    asm("fma.rn.f32x2 %0, %1, %2, %3;" : "=l"(d) : "l"(a), "l"(b), "l"(c));
    return d;
}
__device__ __forceinline__ float2 unpack2(u64 v) {
    float2 r;
    asm("mov.b64 {%0, %1}, %2;" : "=f"(r.x), "=f"(r.y) : "l"(v));
    return r;
}
__device__ __forceinline__ void st_cluster_f32(float* p, int rank, float v) {
    uint32_t la = (uint32_t)__cvta_generic_to_shared(p);
    uint32_t ra;
    asm volatile("mapa.shared::cluster.u32 %0, %1, %2;" : "=r"(ra) : "r"(la), "r"(rank));
    asm volatile("st.shared::cluster.f32 [%0], %1;" :: "r"(ra), "f"(v) : "memory");
}
__device__ __forceinline__ void mbar_init(uint32_t a, uint32_t cnt) {
    asm volatile("mbarrier.init.shared.b64 [%0], %1;" :: "r"(a), "r"(cnt) : "memory");
}
__device__ __forceinline__ void mbar_arrive_rank(uint32_t local_addr, uint32_t rank) {
    asm volatile(
        "{\n\t.reg .b32 ra;\n\t"
        "mapa.shared::cluster.u32 ra, %0, %1;\n\t"
        "mbarrier.arrive.release.cluster.shared::cluster.b64 _, [ra];\n\t}"
        :: "r"(local_addr), "r"(rank) : "memory");
}
__device__ __forceinline__ void mbar_wait(uint32_t addr, uint32_t parity) {
    asm volatile(
        "{\n\t.reg .pred P;\n"
        "WL_%=:\n\t"
        "mbarrier.try_wait.parity.acquire.cluster.shared::cta.b64 P, [%0], %1, 0x989680;\n\t"
        "@P bra WD_%=;\n\t"
        "bra WL_%=;\n"
        "WD_%=:\n\t}"
        :: "r"(addr), "r"(parity) : "memory");
}
__device__ __forceinline__ void cluster_sync_() {
    asm volatile("barrier.cluster.arrive.aligned;" ::: "memory");
    asm volatile("barrier.cluster.wait.aligned;" ::: "memory");
}

// ---------------------------------------------------------------------------
// Phase 1: 32 clusters x 4 CTAs, 4 batches/cluster, 256 threads/CTA.
// Layer-1 weights (64KB slice) in SMEM; layer-2 weights (128KB slice) fully
// register-resident: thread vr owns one gate row of (Wih2|Whh2), 64 u64 regs.
// ---------------------------------------------------------------------------
__global__ void __launch_bounds__(256, 1) __cluster_dims__(4, 1, 1)
lstm_seq_kernel(const float* __restrict__ x,
                const float* __restrict__ Wih1, const float* __restrict__ Whh1,
                const float* __restrict__ bih1, const float* __restrict__ bhh1,
                const float* __restrict__ Wih2, const float* __restrict__ Whh2,
                const float* __restrict__ bih2, const float* __restrict__ bhh2)
{
    extern __shared__ float sW1[];                  // [128][W1STRIDE]

    __shared__ __align__(16) float h1buf[2][GB][HDIM];
    __shared__ __align__(16) float c1buf[2][GB][HDIM];
    __shared__ __align__(16) float h2buf[2][GB][HDIM];
    __shared__ float xs[GB][TSEQ];
    __shared__ __align__(16) float gbuf[512];       // layer-1 gates [row*4+b]
    __shared__ __align__(16) float part2[256 * 4];  // layer-2 dots [vrow*4+b]
    __shared__ float bias1s[128], bias2s[128], wih1s[128];
    __shared__ __align__(8) u64 mbar[2];

    const int tid  = threadIdx.x;
    const int rank = blockIdx.x & 3;
    const int bg0  = (blockIdx.x >> 2) * GB;

    // roles
    const int j1 = (tid & 15) | ((tid >> 5) << 4);  // mv1 local row 0..127
    const int kh = (tid >> 4) & 1;                  // mv1 k-half (warp-half)
    const int m2 = tid >> 7;                        // mv2: 0 = Wih2, 1 = Whh2
    const int r2 = tid & 127;                       // mv2 local row
    const int cu = tid & 31, cb = tid >> 5;         // cell roles (tid<128)
    const int slot = rank * 32 + cu;

    // ---- layer-2 weights -> registers (64 u64 = one full row)
    u64 w2[64];
    {
        const int gr2 = (r2 >> 5) * 128 + rank * 32 + (r2 & 31);
        const float* src2 = (m2 ? Whh2 : Wih2) + (size_t)gr2 * 128;
        #pragma unroll
        for (int k = 0; k < 32; k++) {
            ulonglong2 v = ((const ulonglong2*)src2)[k];
            w2[2 * k] = v.x; w2[2 * k + 1] = v.y;
        }
    }

    // ---- layer-1 weight slice -> SMEM
    for (int idx = tid; idx < 128 * 32; idx += 256) {
        int j = idx >> 5, k4 = idx & 31;
        int gr = (j >> 5) * 128 + rank * 32 + (j & 31);
        ((float4*)(sW1 + j * W1STRIDE))[k4] = ((const float4*)(Whh1 + (size_t)gr * 128))[k4];
    }
    if (tid < 128) {
        int gr = (tid >> 5) * 128 + rank * 32 + (tid & 31);
        bias1s[tid] = bih1[gr] + bhh1[gr];
        bias2s[tid] = bih2[gr] + bhh2[gr];
        wih1s[tid]  = Wih1[gr];
    }
    for (int idx = tid; idx < GB * TSEQ; idx += 256) {
        int b = idx >> 9, tt = idx & (TSEQ - 1);
        xs[b][tt] = x[(size_t)(bg0 + b) * TSEQ + tt];
    }
    for (int idx = tid; idx < 2 * GB * HDIM; idx += 256) {
        ((float*)h1buf)[idx] = 0.f;
        ((float*)c1buf)[idx] = 0.f;
        ((float*)h2buf)[idx] = 0.f;
    }
    const uint32_t mb1a = (uint32_t)__cvta_generic_to_shared(&mbar[0]);
    const uint32_t mb2a = (uint32_t)__cvta_generic_to_shared(&mbar[1]);
    if (tid == 0) { mbar_init(mb1a, 4); mbar_init(mb2a, 4); }
    __syncthreads();
    cluster_sync_();

    float c1s = 0.f, c2s = 0.f;
    int p = 0;
    float* g_h2p = g_h2 + (size_t)(bg0 + cb) * HDIM + slot;

    for (int t = 0; t < TSEQ; t++) {
        const int pn = p ^ 1;
        const uint32_t par = (uint32_t)(t & 1);

        // ========== layer 1 matvec: row j1, k-half kh, 4 batches ==========
        {
            const ulonglong2* wp = (const ulonglong2*)(sW1 + j1 * W1STRIDE + kh * 64);
            const ulonglong2* h0 = (const ulonglong2*)(&h1buf[p][0][kh * 64]);
            const ulonglong2* h1v = (const ulonglong2*)(&h1buf[p][1][kh * 64]);
            const ulonglong2* h2v = (const ulonglong2*)(&h1buf[p][2][kh * 64]);
            const ulonglong2* h3v = (const ulonglong2*)(&h1buf[p][3][kh * 64]);
            u64 a0 = 0, a1 = 0, a2 = 0, a3 = 0;
            #pragma unroll
            for (int k = 0; k < 16; k++) {
                ulonglong2 w = wp[k];
                ulonglong2 v0 = h0[k], v1 = h1v[k], v2 = h2v[k], v3 = h3v[k];
                a0 = ffma2(w.x, v0.x, a0); a0 = ffma2(w.y, v0.y, a0);
                a1 = ffma2(w.x, v1.x, a1); a1 = ffma2(w.y, v1.y, a1);
                a2 = ffma2(w.x, v2.x, a2); a2 = ffma2(w.y, v2.y, a2);
                a3 = ffma2(w.x, v3.x, a3); a3 = ffma2(w.y, v3.y, a3);
            }
            float2 f0 = unpack2(a0), f1 = unpack2(a1), f2 = unpack2(a2), f3 = unpack2(a3);
            float s0 = f0.x + f0.y, s1 = f1.x + f1.y, s2 = f2.x + f2.y, s3 = f3.x + f3.y;
            s0 += __shfl_xor_sync(0xffffffffu, s0, 16);
            s1 += __shfl_xor_sync(0xffffffffu, s1, 16);
            s2 += __shfl_xor_sync(0xffffffffu, s2, 16);
            s3 += __shfl_xor_sync(0xffffffffu, s3, 16);
            if (kh == 0)
                *(float4*)&gbuf[j1 * 4] = make_float4(s0, s1, s2, s3);
        }
        __syncthreads();

        // ========== cell 1 (tid<128) ==========
        if (tid < 128) {
            float xv = xs[cb][t];
            float gi = gbuf[(cu)      * 4 + cb] + fmaf(wih1s[cu],      xv, bias1s[cu]);
            float gf = gbuf[(32 + cu) * 4 + cb] + fmaf(wih1s[32 + cu], xv, bias1s[32 + cu]);
            float gg = gbuf[(64 + cu) * 4 + cb] + fmaf(wih1s[64 + cu], xv, bias1s[64 + cu]);
            float go = gbuf[(96 + cu) * 4 + cb] + fmaf(wih1s[96 + cu], xv, bias1s[96 + cu]);
            c1s = sigm(gf) * c1s + sigm(gi) * tanh_fast(gg);
            float h1n = sigm(go) * tanh_fast(c1s);
            #pragma unroll
            for (int r = 0; r < 4; r++) {
                st_cluster_f32(&h1buf[pn][cb][slot], r, h1n);
                st_cluster_f32(&c1buf[pn][cb][slot], r, c1s);
            }
            asm volatile("bar.sync 1, 128;" ::: "memory");
            if (tid == 0) {
                asm volatile("fence.acq_rel.cluster;" ::: "memory");
                #pragma unroll
                for (int r = 0; r < 4; r++) mbar_arrive_rank(mb1a, r);
            }
        }
        mbar_wait(mb1a, par);

        // ========== layer 2 matvec: full row r2 of (Wih2|Whh2), 4 batches ====
        {
            const float* inb = m2 ? &h2buf[p][0][0] : &c1buf[pn][0][0];
            const ulonglong2* i0 = (const ulonglong2*)(inb + 0 * HDIM);
            const ulonglong2* i1 = (const ulonglong2*)(inb + 1 * HDIM);
            const ulonglong2* i2 = (const ulonglong2*)(inb + 2 * HDIM);
            const ulonglong2* i3 = (const ulonglong2*)(inb + 3 * HDIM);
            u64 a0 = 0, a1 = 0, a2 = 0, a3 = 0;
            #pragma unroll
            for (int k = 0; k < 32; k++) {
                ulonglong2 v0 = i0[k], v1 = i1[k], v2 = i2[k], v3 = i3[k];
                u64 wa = w2[2 * k], wb = w2[2 * k + 1];
                a0 = ffma2(wa, v0.x, a0); a0 = ffma2(wb, v0.y, a0);
                a1 = ffma2(wa, v1.x, a1); a1 = ffma2(wb, v1.y, a1);
                a2 = ffma2(wa, v2.x, a2); a2 = ffma2(wb, v2.y, a2);
                a3 = ffma2(wa, v3.x, a3); a3 = ffma2(wb, v3.y, a3);
            }
            float2 f0 = unpack2(a0), f1 = unpack2(a1), f2 = unpack2(a2), f3 = unpack2(a3);
            *(float4*)&part2[tid * 4] = make_float4(f0.x + f0.y, f1.x + f1.y,
                                                    f2.x + f2.y, f3.x + f3.y);
        }
        __syncthreads();

        // ========== cell 2 (tid<128) ==========
        if (tid < 128) {
            float gi = part2[(cu)       * 4 + cb] + part2[(512 + cu * 4)  + cb] + bias2s[cu];
            float gf = part2[(32 + cu)  * 4 + cb] + part2[(512 + (32 + cu) * 4) + cb] + bias2s[32 + cu];
            float gg = part2[(64 + cu)  * 4 + cb] + part2[(512 + (64 + cu) * 4) + cb] + bias2s[64 + cu];
            float go = part2[(96 + cu)  * 4 + cb] + part2[(512 + (96 + cu) * 4) + cb] + bias2s[96 + cu];
            c2s = sigm(gf) * c2s + sigm(gi) * tanh_fast(gg);
            float h2n = sigm(go) * tanh_fast(c2s);
            #pragma unroll
            for (int r = 0; r < 4; r++)
                st_cluster_f32(&h2buf[pn][cb][slot], r, h2n);
            g_h2p[(size_t)t * (BATCH * HDIM)] = h2n;
            asm volatile("bar.sync 1, 128;" ::: "memory");
            if (tid == 0) {
                asm volatile("fence.acq_rel.cluster;" ::: "memory");
                #pragma unroll
                for (int r = 0; r < 4; r++) mbar_arrive_rank(mb2a, r);
            }
        }
        mbar_wait(mb2a, par);
        p ^= 1;
    }
}

// ---------------------------------------------------------------------------
__global__ void dots_kernel(const float* __restrict__ w_t)
{
    int gid  = blockIdx.x * blockDim.x + threadIdx.x;
    int gw   = gid >> 5;
    int lane = gid & 31;
    if (gw >= TSEQ * BATCH) return;
    float4 h = *(const float4*)(g_h2 + (size_t)gw * HDIM + lane * 4);
    float4 a = *(const float4*)(w_t + lane * 4);
    float4 o = *(const float4*)(w_t + HDIM + lane * 4);
    float dh   = h.x * a.x + h.y * a.y + h.z * a.z + h.w * a.w;
    float dold = h.x * o.x + h.y * o.y + h.z * o.z + h.w * o.w;
    #pragma unroll
    for (int off = 16; off; off >>= 1) {
        dh   += __shfl_down_sync(0xffffffffu, dh, off);
        dold += __shfl_down_sync(0xffffffffu, dold, off);
    }
    if (lane == 0) { g_dh[gw] = dh; g_dold[gw] = dold; }
}

// ---------------------------------------------------------------------------
__global__ void __launch_bounds__(256, 1)
attn_fc_kernel(const float* __restrict__ fcW, const float* __restrict__ fcb,
               float* __restrict__ out)
{
    extern __shared__ float sm[];
    float* sFcT = sm;                       // [128][132]
    float* sPre = sFcT + 128 * RSTRIDE;     // [128][132]
    float* sE   = sPre + 128 * RSTRIDE;     // [33][128]
    float* sHd  = sE + 33 * 128;            // [128]
    float* sFcb = sHd + 128;                // [128]
    float* sRed = sFcb + 128;               // [256]

    const int t    = blockIdx.x;
    const int tid  = threadIdx.x;
    const int lane = tid & 31;
    const int warp = tid >> 5;

    for (int idx = tid; idx < 128 * 128; idx += 256) {
        int c = idx >> 7, h = idx & 127;
        sFcT[h * RSTRIDE + c] = fcW[idx];
    }
    if (tid < 128) {
        sFcb[tid] = fcb[tid];
        sHd[tid]  = g_dh[t * BATCH + tid];
    }
    __syncthreads();

    const int s_min = (t < 32) ? (32 - t) : 0;
    const int nsc   = (33 - s_min) * 128;
    float lmax = -1e30f;
    for (int n = tid; n < nsc; n += 256) {
        int s = s_min + (n >> 7), b = n & 127;
        int idx = t - 33 + s;
        float sc = sHd[b] + (idx >= 0 ? g_dold[idx * BATCH + b] : 0.f);
        sE[s * 128 + b] = sc;
        lmax = fmaxf(lmax, sc);
    }
    sRed[tid] = lmax; __syncthreads();
    for (int off = 128; off; off >>= 1) {
        if (tid < off) sRed[tid] = fmaxf(sRed[tid], sRed[tid + off]);
        __syncthreads();
    }
    float mx = sRed[0];
    __syncthreads();
    float lsum = 0.f;
    for (int n = tid; n < nsc; n += 256) {
        int s = s_min + (n >> 7), b = n & 127;
        float e = __expf(sE[s * 128 + b] - mx);
        sE[s * 128 + b] = e;
        lsum += e;
    }
    sRed[tid] = lsum; __syncthreads();
    for (int off = 128; off; off >>= 1) {
        if (tid < off) sRed[tid] += sRed[tid + off];
        __syncthreads();
    }
    float inv = __fdividef(1.f, sRed[0]);
    __syncthreads();

    const int s_att = (t < 33) ? (33 - t) : 0;
    for (int b = warp; b < 128; b += 8) {
        float4 acc; acc.x = acc.y = acc.z = acc.w = 0.f;
        for (int s = s_att; s < 33; s++) {
            float w  = sE[s * 128 + b];
            float4 v = *(const float4*)(g_h2 + (size_t)(t - 33 + s) * (BATCH * HDIM)
                                              + (size_t)b * HDIM + lane * 4);
            acc.x += w * v.x; acc.y += w * v.y; acc.z += w * v.z; acc.w += w * v.w;
        }
        float4 hc = *(const float4*)(g_h2 + (size_t)t * (BATCH * HDIM)
                                           + (size_t)b * HDIM + lane * 4);
        float4 pre;
        pre.x = hc.x + inv * acc.x; pre.y = hc.y + inv * acc.y;
        pre.z = hc.z + inv * acc.z; pre.w = hc.w + inv * acc.w;
        *(float4*)(sPre + b * RSTRIDE + lane * 4) = pre;
    }
    __syncthreads();

    const int c0 = lane * 4;
    float4 bias = *(const float4*)(sFcb + c0);
    for (int r = 0; r < 4; r++) {
        int b0 = (warp + 8 * r) * 4;
        float4 a0, a1, a2, a3;
        a0.x=a0.y=a0.z=a0.w=0.f; a1=a0; a2=a0; a3=a0;
        const float4* p0 = (const float4*)(sPre + (size_t)(b0 + 0) * RSTRIDE);
        const float4* p1 = (const float4*)(sPre + (size_t)(b0 + 1) * RSTRIDE);
        const float4* p2 = (const float4*)(sPre + (size_t)(b0 + 2) * RSTRIDE);
        const float4* p3 = (const float4*)(sPre + (size_t)(b0 + 3) * RSTRIDE);
        #pragma unroll
        for (int h4 = 0; h4 < 32; h4++) {
            float4 q0 = p0[h4], q1 = p1[h4], q2 = p2[h4], q3 = p3[h4];
            #pragma unroll
            for (int hh = 0; hh < 4; hh++) {
                float4 w = *(const float4*)(sFcT + (h4 * 4 + hh) * RSTRIDE + c0);
                float v0 = (&q0.x)[hh], v1 = (&q1.x)[hh], v2 = (&q2.x)[hh], v3 = (&q3.x)[hh];
                a0.x += v0 * w.x; a0.y += v0 * w.y; a0.z += v0 * w.z; a0.w += v0 * w.w;
                a1.x += v1 * w.x; a1.y += v1 * w.y; a1.z += v1 * w.z; a1.w += v1 * w.w;
                a2.x += v2 * w.x; a2.y += v2 * w.y; a2.z += v2 * w.z; a2.w += v2 * w.w;
                a3.x += v3 * w.x; a3.y += v3 * w.y; a3.z += v3 * w.z; a3.w += v3 * w.w;
            }
        }
        a0.x += bias.x; a0.y += bias.y; a0.z += bias.z; a0.w += bias.w;
        a1.x += bias.x; a1.y += bias.y; a1.z += bias.z; a1.w += bias.w;
        a2.x += bias.x; a2.y += bias.y; a2.z += bias.z; a2.w += bias.w;
        a3.x += bias.x; a3.y += bias.y; a3.z += bias.z; a3.w += bias.w;
        size_t obase = (size_t)t * 128 + c0;
        *(float4*)(out + (size_t)(b0 + 0) * (TSEQ * 128) + obase) = a0;
        *(float4*)(out + (size_t)(b0 + 1) * (TSEQ * 128) + obase) = a1;
        *(float4*)(out + (size_t)(b0 + 2) * (TSEQ * 128) + obase) = a2;
        *(float4*)(out + (size_t)(b0 + 3) * (TSEQ * 128) + obase) = a3;
    }
}

// ---------------------------------------------------------------------------
extern "C" void kernel_launch(void* const* d_in, const int* in_sizes, int n_in,
                              void* d_out, int out_size)
{
    const float* x    = (const float*)d_in[0];
    const float* Wih1 = (const float*)d_in[1];
    const float* Whh1 = (const float*)d_in[2];
    const float* bih1 = (const float*)d_in[3];
    const float* bhh1 = (const float*)d_in[4];
    const float* Wih2 = (const float*)d_in[5];
    const float* Whh2 = (const float*)d_in[6];
    const float* bih2 = (const float*)d_in[7];
    const float* bhh2 = (const float*)d_in[8];
    const float* w_t  = (const float*)d_in[9];
    const float* fcW  = (const float*)d_in[10];
    const float* fcb  = (const float*)d_in[11];
    float* out = (float*)d_out;

    const int smem1 = 128 * W1STRIDE * (int)sizeof(float);   // 67584
    const int smem3 = (2 * 128 * RSTRIDE + 33 * 128 + 128 + 128 + 256) * (int)sizeof(float);

    cudaFuncSetAttribute(lstm_seq_kernel, cudaFuncAttributeMaxDynamicSharedMemorySize, smem1);
    cudaFuncSetAttribute(attn_fc_kernel,  cudaFuncAttributeMaxDynamicSharedMemorySize, smem3);

    lstm_seq_kernel<<<128, 256, smem1>>>(x, Wih1, Whh1, bih1, bhh1,
                                         Wih2, Whh2, bih2, bhh2);
    dots_kernel<<<(TSEQ * BATCH * 32) / 256, 256>>>(w_t);
    attn_fc_kernel<<<TSEQ, 256, smem3>>>(fcW, fcb, out);
}

// round 4
// speedup vs baseline: 2.4629x; 1.2561x over previous
#include <cuda_runtime.h>
#include <cstdint>

#define HDIM 128
#define TSEQ 512
#define BATCH 128
#define GB 4
#define RSTRIDE 132
#define W1STRIDE 132

typedef unsigned long long u64;

__device__ float g_h2[(size_t)TSEQ * BATCH * HDIM];   // [t][b][h]
__device__ float g_dold[TSEQ * BATCH];
__device__ float g_dh[TSEQ * BATCH];

__device__ __forceinline__ float sigm(float x) {
    return __fdividef(1.f, 1.f + __expf(-x));
}
__device__ __forceinline__ float tanh_fast(float x) {
    x = fminf(fmaxf(x, -15.f), 15.f);
    float e = __expf(2.f * x);
    return __fdividef(e - 1.f, e + 1.f);
}
__device__ __forceinline__ u64 ffma2(u64 a, u64 b, u64 c) {
    u64 d;
    asm("fma.rn.f32x2 %0, %1, %2, %3;" : "=l"(d) : "l"(a), "l"(b), "l"(c));
    return d;
}
__device__ __forceinline__ float2 unpack2(u64 v) {
    float2 r;
    asm("mov.b64 {%0, %1}, %2;" : "=f"(r.x), "=f"(r.y) : "l"(v));
    return r;
}
__device__ __forceinline__ void st_cluster_f32(float* p, int rank, float v) {
    uint32_t la = (uint32_t)__cvta_generic_to_shared(p);
    uint32_t ra;
    asm volatile("mapa.shared::cluster.u32 %0, %1, %2;" : "=r"(ra) : "r"(la), "r"(rank));
    asm volatile("st.shared::cluster.f32 [%0], %1;" :: "r"(ra), "f"(v) : "memory");
}
__device__ __forceinline__ void mbar_init(uint32_t a, uint32_t cnt) {
    asm volatile("mbarrier.init.shared.b64 [%0], %1;" :: "r"(a), "r"(cnt) : "memory");
}
__device__ __forceinline__ void mbar_arrive_rank(uint32_t local_addr, uint32_t rank) {
    asm volatile(
        "{\n\t.reg .b32 ra;\n\t"
        "mapa.shared::cluster.u32 ra, %0, %1;\n\t"
        "mbarrier.arrive.release.cluster.shared::cluster.b64 _, [ra];\n\t}"
        :: "r"(local_addr), "r"(rank) : "memory");
}
__device__ __forceinline__ void mbar_wait(uint32_t addr, uint32_t parity) {
    asm volatile(
        "{\n\t.reg .pred P;\n"
        "WL_%=:\n\t"
        "mbarrier.try_wait.parity.acquire.cluster.shared::cta.b64 P, [%0], %1, 0x989680;\n\t"
        "@P bra WD_%=;\n\t"
        "bra WL_%=;\n"
        "WD_%=:\n\t}"
        :: "r"(addr), "r"(parity) : "memory");
}
__device__ __forceinline__ void cluster_sync_() {
    asm volatile("barrier.cluster.arrive.aligned;" ::: "memory");
    asm volatile("barrier.cluster.wait.aligned;" ::: "memory");
}

// ---------------------------------------------------------------------------
// Phase 1: 32 clusters x 4 CTAs, 4 batches/cluster, 256 threads/CTA.
// Software-pipelined: iteration i computes cell1(step i) and cell2(step i-1),
// so both matvecs depend only on last iteration's broadcast -> ONE cluster
// handshake per iteration, and the two cell updates run on disjoint warps.
// Layer-1 weights in SMEM (conflict-free), layer-2 weights in registers.
// ---------------------------------------------------------------------------
__global__ void __launch_bounds__(256, 1) __cluster_dims__(4, 1, 1)
lstm_seq_kernel(const float* __restrict__ x,
                const float* __restrict__ Wih1, const float* __restrict__ Whh1,
                const float* __restrict__ bih1, const float* __restrict__ bhh1,
                const float* __restrict__ Wih2, const float* __restrict__ Whh2,
                const float* __restrict__ bih2, const float* __restrict__ bhh2)
{
    extern __shared__ float sW1[];                  // [128][W1STRIDE]

    __shared__ __align__(16) float h1bc[2][GB][HDIM];
    __shared__ __align__(16) float c1bc[2][GB][HDIM];
    __shared__ __align__(16) float h2bc[2][GB][HDIM];
    __shared__ float xs[GB][TSEQ];
    __shared__ __align__(16) float gbuf[512];       // layer-1 gates [row*4+b]
    __shared__ __align__(16) float part2[256 * 4];  // layer-2 dots [vrow*4+b]
    __shared__ float bias1s[128], bias2s[128], wih1s[128];
    __shared__ __align__(8) u64 mbar[1];

    const int tid  = threadIdx.x;
    const int rank = blockIdx.x & 3;
    const int bg0  = (blockIdx.x >> 2) * GB;

    // roles
    const int j1 = (tid & 15) | ((tid >> 5) << 4);  // mv1 local row 0..127
    const int kh = (tid >> 4) & 1;                  // mv1 k-half
    const int m2 = tid >> 7;                        // mv2: 0=Wih2 row, 1=Whh2 row
    const int r2 = tid & 127;                       // mv2 local row
    const int cu  = tid & 31,          cb  = tid >> 5;          // cell1 (tid<128)
    const int cu2 = (tid - 128) & 31,  cb2 = (tid - 128) >> 5;  // cell2 (tid>=128)
    const int slot1 = rank * 32 + cu;
    const int slot2 = rank * 32 + cu2;

    // ---- layer-2 weights -> registers (64 u64 = one full gate row)
    u64 w2[64];
    {
        const int gr2 = (r2 >> 5) * 128 + rank * 32 + (r2 & 31);
        const float* src2 = (m2 ? Whh2 : Wih2) + (size_t)gr2 * 128;
        #pragma unroll
        for (int k = 0; k < 32; k++) {
            ulonglong2 v = ((const ulonglong2*)src2)[k];
            w2[2 * k] = v.x; w2[2 * k + 1] = v.y;
        }
    }

    // ---- layer-1 weight slice -> SMEM
    for (int idx = tid; idx < 128 * 32; idx += 256) {
        int j = idx >> 5, k4 = idx & 31;
        int gr = (j >> 5) * 128 + rank * 32 + (j & 31);
        ((float4*)(sW1 + j * W1STRIDE))[k4] = ((const float4*)(Whh1 + (size_t)gr * 128))[k4];
    }
    if (tid < 128) {
        int gr = (tid >> 5) * 128 + rank * 32 + (tid & 31);
        bias1s[tid] = bih1[gr] + bhh1[gr];
        bias2s[tid] = bih2[gr] + bhh2[gr];
        wih1s[tid]  = Wih1[gr];
    }
    for (int idx = tid; idx < GB * TSEQ; idx += 256) {
        int b = idx >> 9, tt = idx & (TSEQ - 1);
        xs[b][tt] = x[(size_t)(bg0 + b) * TSEQ + tt];
    }
    for (int idx = tid; idx < 2 * GB * HDIM; idx += 256) {
        ((float*)h1bc)[idx] = 0.f;
        ((float*)c1bc)[idx] = 0.f;
        ((float*)h2bc)[idx] = 0.f;
    }
    const uint32_t mba = (uint32_t)__cvta_generic_to_shared(&mbar[0]);
    if (tid == 0) mbar_init(mba, 4);
    __syncthreads();
    cluster_sync_();   // peers see zeroed buffers + initialized mbarrier

    float c1s = 0.f, c2s = 0.f;
    int p = 0;
    float* g_h2p = g_h2 + (size_t)(bg0 + cb2) * HDIM + slot2;

    for (int i = 0; i <= TSEQ; i++) {
        const int pn = p ^ 1;
        const uint32_t par = (uint32_t)(i & 1);

        // ===== mv1: gates1(i) partial = W1_row(j1, half kh) . h1(i-1) =====
        if (i < TSEQ) {
            const ulonglong2* wp = (const ulonglong2*)(sW1 + j1 * W1STRIDE + kh * 64);
            const ulonglong2* h0 = (const ulonglong2*)(&h1bc[p][0][kh * 64]);
            const ulonglong2* h1v = (const ulonglong2*)(&h1bc[p][1][kh * 64]);
            const ulonglong2* h2v = (const ulonglong2*)(&h1bc[p][2][kh * 64]);
            const ulonglong2* h3v = (const ulonglong2*)(&h1bc[p][3][kh * 64]);
            u64 a0 = 0, a1 = 0, a2 = 0, a3 = 0;
            #pragma unroll
            for (int k = 0; k < 16; k++) {
                ulonglong2 w = wp[k];
                ulonglong2 v0 = h0[k], v1 = h1v[k], v2 = h2v[k], v3 = h3v[k];
                a0 = ffma2(w.x, v0.x, a0); a0 = ffma2(w.y, v0.y, a0);
                a1 = ffma2(w.x, v1.x, a1); a1 = ffma2(w.y, v1.y, a1);
                a2 = ffma2(w.x, v2.x, a2); a2 = ffma2(w.y, v2.y, a2);
                a3 = ffma2(w.x, v3.x, a3); a3 = ffma2(w.y, v3.y, a3);
            }
            float2 f0 = unpack2(a0), f1 = unpack2(a1), f2 = unpack2(a2), f3 = unpack2(a3);
            float s0 = f0.x + f0.y, s1 = f1.x + f1.y, s2 = f2.x + f2.y, s3 = f3.x + f3.y;
            s0 += __shfl_xor_sync(0xffffffffu, s0, 16);
            s1 += __shfl_xor_sync(0xffffffffu, s1, 16);
            s2 += __shfl_xor_sync(0xffffffffu, s2, 16);
            s3 += __shfl_xor_sync(0xffffffffu, s3, 16);
            if (kh == 0)
                *(float4*)&gbuf[j1 * 4] = make_float4(s0, s1, s2, s3);
        }

        // ===== mv2: dots for step i-1: Wih2_row . c1(i-1) | Whh2_row . h2(i-2) =====
        if (i > 0) {
            const float* inb = m2 ? &h2bc[p][0][0] : &c1bc[p][0][0];
            const ulonglong2* i0 = (const ulonglong2*)(inb + 0 * HDIM);
            const ulonglong2* i1 = (const ulonglong2*)(inb + 1 * HDIM);
            const ulonglong2* i2 = (const ulonglong2*)(inb + 2 * HDIM);
            const ulonglong2* i3 = (const ulonglong2*)(inb + 3 * HDIM);
            u64 a0 = 0, a1 = 0, a2 = 0, a3 = 0;
            #pragma unroll
            for (int k = 0; k < 32; k++) {
                ulonglong2 v0 = i0[k], v1 = i1[k], v2 = i2[k], v3 = i3[k];
                u64 wa = w2[2 * k], wb = w2[2 * k + 1];
                a0 = ffma2(wa, v0.x, a0); a0 = ffma2(wb, v0.y, a0);
                a1 = ffma2(wa, v1.x, a1); a1 = ffma2(wb, v1.y, a1);
                a2 = ffma2(wa, v2.x, a2); a2 = ffma2(wb, v2.y, a2);
                a3 = ffma2(wa, v3.x, a3); a3 = ffma2(wb, v3.y, a3);
            }
            float2 f0 = unpack2(a0), f1 = unpack2(a1), f2 = unpack2(a2), f3 = unpack2(a3);
            *(float4*)&part2[tid * 4] = make_float4(f0.x + f0.y, f1.x + f1.y,
                                                    f2.x + f2.y, f3.x + f3.y);
        }
        __syncthreads();

        // ===== cell1 (tid<128): step i ===== | ===== cell2 (tid>=128): step i-1 =====
        if (tid < 128) {
            if (i < TSEQ) {
                float xv = xs[cb][i];
                float gi = gbuf[(cu)      * 4 + cb] + fmaf(wih1s[cu],      xv, bias1s[cu]);
                float gf = gbuf[(32 + cu) * 4 + cb] + fmaf(wih1s[32 + cu], xv, bias1s[32 + cu]);
                float gg = gbuf[(64 + cu) * 4 + cb] + fmaf(wih1s[64 + cu], xv, bias1s[64 + cu]);
                float go = gbuf[(96 + cu) * 4 + cb] + fmaf(wih1s[96 + cu], xv, bias1s[96 + cu]);
                c1s = sigm(gf) * c1s + sigm(gi) * tanh_fast(gg);
                float h1n = sigm(go) * tanh_fast(c1s);
                #pragma unroll
                for (int r = 0; r < 4; r++) {
                    st_cluster_f32(&h1bc[pn][cb][slot1], r, h1n);
                    st_cluster_f32(&c1bc[pn][cb][slot1], r, c1s);
                }
            }
        } else {
            if (i > 0) {
                float gi = part2[(cu2)      * 4 + cb2] + part2[(128 + cu2)       * 4 + cb2] + bias2s[cu2];
                float gf = part2[(32 + cu2) * 4 + cb2] + part2[(128 + 32 + cu2)  * 4 + cb2] + bias2s[32 + cu2];
                float gg = part2[(64 + cu2) * 4 + cb2] + part2[(128 + 64 + cu2)  * 4 + cb2] + bias2s[64 + cu2];
                float go = part2[(96 + cu2) * 4 + cb2] + part2[(128 + 96 + cu2)  * 4 + cb2] + bias2s[96 + cu2];
                c2s = sigm(gf) * c2s + sigm(gi) * tanh_fast(gg);
                float h2n = sigm(go) * tanh_fast(c2s);
                #pragma unroll
                for (int r = 0; r < 4; r++)
                    st_cluster_f32(&h2bc[pn][cb2][slot2], r, h2n);
                g_h2p[(size_t)(i - 1) * (BATCH * HDIM)] = h2n;
            }
        }
        __syncthreads();
        if (tid == 0) {
            asm volatile("fence.acq_rel.cluster;" ::: "memory");
            #pragma unroll
            for (int r = 0; r < 4; r++) mbar_arrive_rank(mba, r);
        }
        mbar_wait(mba, par);
        p ^= 1;
    }
}

// ---------------------------------------------------------------------------
__global__ void dots_kernel(const float* __restrict__ w_t)
{
    int gid  = blockIdx.x * blockDim.x + threadIdx.x;
    int gw   = gid >> 5;
    int lane = gid & 31;
    if (gw >= TSEQ * BATCH) return;
    float4 h = *(const float4*)(g_h2 + (size_t)gw * HDIM + lane * 4);
    float4 a = *(const float4*)(w_t + lane * 4);
    float4 o = *(const float4*)(w_t + HDIM + lane * 4);
    float dh   = h.x * a.x + h.y * a.y + h.z * a.z + h.w * a.w;
    float dold = h.x * o.x + h.y * o.y + h.z * o.z + h.w * o.w;
    #pragma unroll
    for (int off = 16; off; off >>= 1) {
        dh   += __shfl_down_sync(0xffffffffu, dh, off);
        dold += __shfl_down_sync(0xffffffffu, dold, off);
    }
    if (lane == 0) { g_dh[gw] = dh; g_dold[gw] = dold; }
}

// ---------------------------------------------------------------------------
__global__ void __launch_bounds__(256, 1)
attn_fc_kernel(const float* __restrict__ fcW, const float* __restrict__ fcb,
               float* __restrict__ out)
{
    extern __shared__ float sm[];
    float* sFcT = sm;                       // [128][132]
    float* sPre = sFcT + 128 * RSTRIDE;     // [128][132]
    float* sE   = sPre + 128 * RSTRIDE;     // [33][128]
    float* sHd  = sE + 33 * 128;            // [128]
    float* sFcb = sHd + 128;                // [128]
    float* sRed = sFcb + 128;               // [256]

    const int t    = blockIdx.x;
    const int tid  = threadIdx.x;
    const int lane = tid & 31;
    const int warp = tid >> 5;

    for (int idx = tid; idx < 128 * 128; idx += 256) {
        int c = idx >> 7, h = idx & 127;
        sFcT[h * RSTRIDE + c] = fcW[idx];
    }
    if (tid < 128) {
        sFcb[tid] = fcb[tid];
        sHd[tid]  = g_dh[t * BATCH + tid];
    }
    __syncthreads();

    const int s_min = (t < 32) ? (32 - t) : 0;
    const int nsc   = (33 - s_min) * 128;
    float lmax = -1e30f;
    for (int n = tid; n < nsc; n += 256) {
        int s = s_min + (n >> 7), b = n & 127;
        int idx = t - 33 + s;
        float sc = sHd[b] + (idx >= 0 ? g_dold[idx * BATCH + b] : 0.f);
        sE[s * 128 + b] = sc;
        lmax = fmaxf(lmax, sc);
    }
    sRed[tid] = lmax; __syncthreads();
    for (int off = 128; off; off >>= 1) {
        if (tid < off) sRed[tid] = fmaxf(sRed[tid], sRed[tid + off]);
        __syncthreads();
    }
    float mx = sRed[0];
    __syncthreads();
    float lsum = 0.f;
    for (int n = tid; n < nsc; n += 256) {
        int s = s_min + (n >> 7), b = n & 127;
        float e = __expf(sE[s * 128 + b] - mx);
        sE[s * 128 + b] = e;
        lsum += e;
    }
    sRed[tid] = lsum; __syncthreads();
    for (int off = 128; off; off >>= 1) {
        if (tid < off) sRed[tid] += sRed[tid + off];
        __syncthreads();
    }
    float inv = __fdividef(1.f, sRed[0]);
    __syncthreads();

    const int s_att = (t < 33) ? (33 - t) : 0;
    for (int b = warp; b < 128; b += 8) {
        float4 acc; acc.x = acc.y = acc.z = acc.w = 0.f;
        for (int s = s_att; s < 33; s++) {
            float w  = sE[s * 128 + b];
            float4 v = *(const float4*)(g_h2 + (size_t)(t - 33 + s) * (BATCH * HDIM)
                                              + (size_t)b * HDIM + lane * 4);
            acc.x += w * v.x; acc.y += w * v.y; acc.z += w * v.z; acc.w += w * v.w;
        }
        float4 hc = *(const float4*)(g_h2 + (size_t)t * (BATCH * HDIM)
                                           + (size_t)b * HDIM + lane * 4);
        float4 pre;
        pre.x = hc.x + inv * acc.x; pre.y = hc.y + inv * acc.y;
        pre.z = hc.z + inv * acc.z; pre.w = hc.w + inv * acc.w;
        *(float4*)(sPre + b * RSTRIDE + lane * 4) = pre;
    }
    __syncthreads();

    const int c0 = lane * 4;
    float4 bias = *(const float4*)(sFcb + c0);
    for (int r = 0; r < 4; r++) {
        int b0 = (warp + 8 * r) * 4;
        float4 a0, a1, a2, a3;
        a0.x=a0.y=a0.z=a0.w=0.f; a1=a0; a2=a0; a3=a0;
        const float4* p0 = (const float4*)(sPre + (size_t)(b0 + 0) * RSTRIDE);
        const float4* p1 = (const float4*)(sPre + (size_t)(b0 + 1) * RSTRIDE);
        const float4* p2 = (const float4*)(sPre + (size_t)(b0 + 2) * RSTRIDE);
        const float4* p3 = (const float4*)(sPre + (size_t)(b0 + 3) * RSTRIDE);
        #pragma unroll
        for (int h4 = 0; h4 < 32; h4++) {
            float4 q0 = p0[h4], q1 = p1[h4], q2 = p2[h4], q3 = p3[h4];
            #pragma unroll
            for (int hh = 0; hh < 4; hh++) {
                float4 w = *(const float4*)(sFcT + (h4 * 4 + hh) * RSTRIDE + c0);
                float v0 = (&q0.x)[hh], v1 = (&q1.x)[hh], v2 = (&q2.x)[hh], v3 = (&q3.x)[hh];
                a0.x += v0 * w.x; a0.y += v0 * w.y; a0.z += v0 * w.z; a0.w += v0 * w.w;
                a1.x += v1 * w.x; a1.y += v1 * w.y; a1.z += v1 * w.z; a1.w += v1 * w.w;
                a2.x += v2 * w.x; a2.y += v2 * w.y; a2.z += v2 * w.z; a2.w += v2 * w.w;
                a3.x += v3 * w.x; a3.y += v3 * w.y; a3.z += v3 * w.z; a3.w += v3 * w.w;
            }
        }
        a0.x += bias.x; a0.y += bias.y; a0.z += bias.z; a0.w += bias.w;
        a1.x += bias.x; a1.y += bias.y; a1.z += bias.z; a1.w += bias.w;
        a2.x += bias.x; a2.y += bias.y; a2.z += bias.z; a2.w += bias.w;
        a3.x += bias.x; a3.y += bias.y; a3.z += bias.z; a3.w += bias.w;
        size_t obase = (size_t)t * 128 + c0;
        *(float4*)(out + (size_t)(b0 + 0) * (TSEQ * 128) + obase) = a0;
        *(float4*)(out + (size_t)(b0 + 1) * (TSEQ * 128) + obase) = a1;
        *(float4*)(out + (size_t)(b0 + 2) * (TSEQ * 128) + obase) = a2;
        *(float4*)(out + (size_t)(b0 + 3) * (TSEQ * 128) + obase) = a3;
    }
}

// ---------------------------------------------------------------------------
extern "C" void kernel_launch(void* const* d_in, const int* in_sizes, int n_in,
                              void* d_out, int out_size)
{
    const float* x    = (const float*)d_in[0];
    const float* Wih1 = (const float*)d_in[1];
    const float* Whh1 = (const float*)d_in[2];
    const float* bih1 = (const float*)d_in[3];
    const float* bhh1 = (const float*)d_in[4];
    const float* Wih2 = (const float*)d_in[5];
    const float* Whh2 = (const float*)d_in[6];
    const float* bih2 = (const float*)d_in[7];
    const float* bhh2 = (const float*)d_in[8];
    const float* w_t  = (const float*)d_in[9];
    const float* fcW  = (const float*)d_in[10];
    const float* fcb  = (const float*)d_in[11];
    float* out = (float*)d_out;

    const int smem1 = 128 * W1STRIDE * (int)sizeof(float);   // 67584
    const int smem3 = (2 * 128 * RSTRIDE + 33 * 128 + 128 + 128 + 256) * (int)sizeof(float);

    cudaFuncSetAttribute(lstm_seq_kernel, cudaFuncAttributeMaxDynamicSharedMemorySize, smem1);
    cudaFuncSetAttribute(attn_fc_kernel,  cudaFuncAttributeMaxDynamicSharedMemorySize, smem3);

    lstm_seq_kernel<<<128, 256, smem1>>>(x, Wih1, Whh1, bih1, bhh1,
                                         Wih2, Whh2, bih2, bhh2);
    dots_kernel<<<(TSEQ * BATCH * 32) / 256, 256>>>(w_t);
    attn_fc_kernel<<<TSEQ, 256, smem3>>>(fcW, fcb, out);
}

// round 5
// speedup vs baseline: 2.4735x; 1.0043x over previous
#include <cuda_runtime.h>
#include <cstdint>

#define HDIM 128
#define TSEQ 512
#define BATCH 128
#define GB 4
#define RSTRIDE 132
#define W1STRIDE 132

typedef unsigned long long u64;

__device__ float g_h2[(size_t)TSEQ * BATCH * HDIM];   // [t][b][h]
__device__ float g_dold[TSEQ * BATCH];
__device__ float g_dh[TSEQ * BATCH];

__device__ __forceinline__ float sigm(float x) {
    return __fdividef(1.f, 1.f + __expf(-x));
}
__device__ __forceinline__ float tanh_fast(float x) {
    x = fminf(fmaxf(x, -15.f), 15.f);
    float e = __expf(2.f * x);
    return __fdividef(e - 1.f, e + 1.f);
}
__device__ __forceinline__ u64 ffma2(u64 a, u64 b, u64 c) {
    u64 d;
    asm("fma.rn.f32x2 %0, %1, %2, %3;" : "=l"(d) : "l"(a), "l"(b), "l"(c));
    return d;
}
__device__ __forceinline__ float2 unpack2(u64 v) {
    float2 r;
    asm("mov.b64 {%0, %1}, %2;" : "=f"(r.x), "=f"(r.y) : "l"(v));
    return r;
}
__device__ __forceinline__ void st_cluster_f32(float* p, int rank, float v) {
    uint32_t la = (uint32_t)__cvta_generic_to_shared(p);
    uint32_t ra;
    asm volatile("mapa.shared::cluster.u32 %0, %1, %2;" : "=r"(ra) : "r"(la), "r"(rank));
    asm volatile("st.shared::cluster.f32 [%0], %1;" :: "r"(ra), "f"(v) : "memory");
}
__device__ __forceinline__ void mbar_init(uint32_t a, uint32_t cnt) {
    asm volatile("mbarrier.init.shared.b64 [%0], %1;" :: "r"(a), "r"(cnt) : "memory");
}
__device__ __forceinline__ void mbar_arrive_rank(uint32_t local_addr, uint32_t rank) {
    asm volatile(
        "{\n\t.reg .b32 ra;\n\t"
        "mapa.shared::cluster.u32 ra, %0, %1;\n\t"
        "mbarrier.arrive.release.cluster.shared::cluster.b64 _, [ra];\n\t}"
        :: "r"(local_addr), "r"(rank) : "memory");
}
__device__ __forceinline__ void mbar_wait(uint32_t addr, uint32_t parity) {
    asm volatile(
        "{\n\t.reg .pred P;\n"
        "WL_%=:\n\t"
        "mbarrier.try_wait.parity.acquire.cluster.shared::cta.b64 P, [%0], %1, 0x989680;\n\t"
        "@P bra WD_%=;\n\t"
        "bra WL_%=;\n"
        "WD_%=:\n\t}"
        :: "r"(addr), "r"(parity) : "memory");
}
__device__ __forceinline__ void cluster_sync_() {
    asm volatile("barrier.cluster.arrive.aligned;" ::: "memory");
    asm volatile("barrier.cluster.wait.aligned;" ::: "memory");
}

// ---------------------------------------------------------------------------
// Phase 1: 32 clusters x 4 CTAs, 4 batches/cluster, 256 threads/CTA.
// Pipelined: iteration i computes cell1(step i) [warps 0-3] and cell2(step
// i-1) [warps 4-7] in parallel. Two DSMEM mbarriers: mbar1 gates cell1's
// h1/c1 broadcast (needed by mv1/mv2), mbar2 gates cell2's h2 broadcast
// (needed only by mv2) -> mv1 overlaps cell2's DSMEM propagation.
// No cluster-scope fence: bar.sync + mbarrier.arrive.release.cluster gives
// cumulative release over the group's remote stores (avoids CCTL.IVALL).
// ---------------------------------------------------------------------------
__global__ void __launch_bounds__(256, 1) __cluster_dims__(4, 1, 1)
lstm_seq_kernel(const float* __restrict__ x,
                const float* __restrict__ Wih1, const float* __restrict__ Whh1,
                const float* __restrict__ bih1, const float* __restrict__ bhh1,
                const float* __restrict__ Wih2, const float* __restrict__ Whh2,
                const float* __restrict__ bih2, const float* __restrict__ bhh2)
{
    extern __shared__ float sW1[];                  // [128][W1STRIDE]

    __shared__ __align__(16) float h1bc[2][GB][HDIM];
    __shared__ __align__(16) float c1bc[2][GB][HDIM];
    __shared__ __align__(16) float h2bc[2][GB][HDIM];
    __shared__ float xs[GB][TSEQ];
    __shared__ __align__(16) float gbuf[512];       // layer-1 gates [row*4+b]
    __shared__ __align__(16) float part2[256 * 4];  // layer-2 dots [vrow*4+b]
    __shared__ float bias1s[128], bias2s[128], wih1s[128];
    __shared__ __align__(8) u64 mbar[2];

    const int tid  = threadIdx.x;
    const int rank = blockIdx.x & 3;
    const int bg0  = (blockIdx.x >> 2) * GB;

    // roles
    const int j1 = (tid & 15) | ((tid >> 5) << 4);  // mv1 local row 0..127
    const int kh = (tid >> 4) & 1;                  // mv1 k-half
    const int m2 = tid >> 7;                        // mv2: 0=Wih2 row, 1=Whh2 row
    const int r2 = tid & 127;                       // mv2 local row
    const int cu  = tid & 31,          cb  = tid >> 5;          // cell1 (tid<128)
    const int cu2 = (tid - 128) & 31,  cb2 = (tid - 128) >> 5;  // cell2 (tid>=128)
    const int slot1 = rank * 32 + cu;
    const int slot2 = rank * 32 + cu2;

    // ---- layer-2 weights -> registers (64 u64 = one full gate row)
    u64 w2[64];
    {
        const int gr2 = (r2 >> 5) * 128 + rank * 32 + (r2 & 31);
        const float* src2 = (m2 ? Whh2 : Wih2) + (size_t)gr2 * 128;
        #pragma unroll
        for (int k = 0; k < 32; k++) {
            ulonglong2 v = ((const ulonglong2*)src2)[k];
            w2[2 * k] = v.x; w2[2 * k + 1] = v.y;
        }
    }

    // ---- layer-1 weight slice -> SMEM
    for (int idx = tid; idx < 128 * 32; idx += 256) {
        int j = idx >> 5, k4 = idx & 31;
        int gr = (j >> 5) * 128 + rank * 32 + (j & 31);
        ((float4*)(sW1 + j * W1STRIDE))[k4] = ((const float4*)(Whh1 + (size_t)gr * 128))[k4];
    }
    if (tid < 128) {
        int gr = (tid >> 5) * 128 + rank * 32 + (tid & 31);
        bias1s[tid] = bih1[gr] + bhh1[gr];
        bias2s[tid] = bih2[gr] + bhh2[gr];
        wih1s[tid]  = Wih1[gr];
    }
    for (int idx = tid; idx < GB * TSEQ; idx += 256) {
        int b = idx >> 9, tt = idx & (TSEQ - 1);
        xs[b][tt] = x[(size_t)(bg0 + b) * TSEQ + tt];
    }
    for (int idx = tid; idx < 2 * GB * HDIM; idx += 256) {
        ((float*)h1bc)[idx] = 0.f;
        ((float*)c1bc)[idx] = 0.f;
        ((float*)h2bc)[idx] = 0.f;
    }
    const uint32_t mb1a = (uint32_t)__cvta_generic_to_shared(&mbar[0]);
    const uint32_t mb2a = (uint32_t)__cvta_generic_to_shared(&mbar[1]);
    if (tid == 0) { mbar_init(mb1a, 4); mbar_init(mb2a, 4); }
    __syncthreads();
    cluster_sync_();   // peers see zeroed buffers + initialized mbarriers

    float c1s = 0.f, c2s = 0.f;
    float* g_h2p = g_h2 + (size_t)(bg0 + cb2) * HDIM + slot2;

    for (int i = 0; i <= TSEQ; i++) {
        const int p  = i & 1;        // read-buffer parity
        const int pn = p ^ 1;        // write-buffer parity
        const uint32_t wpar = (uint32_t)(p ^ 1);  // parity of phase i-1

        // ===== wait for h1/c1 of step i-1, then mv1 =====
        if (i > 0) mbar_wait(mb1a, wpar);

        if (i < TSEQ) {
            const ulonglong2* wp = (const ulonglong2*)(sW1 + j1 * W1STRIDE + kh * 64);
            const ulonglong2* h0 = (const ulonglong2*)(&h1bc[p][0][kh * 64]);
            const ulonglong2* h1v = (const ulonglong2*)(&h1bc[p][1][kh * 64]);
            const ulonglong2* h2v = (const ulonglong2*)(&h1bc[p][2][kh * 64]);
            const ulonglong2* h3v = (const ulonglong2*)(&h1bc[p][3][kh * 64]);
            u64 a0 = 0, a1 = 0, a2 = 0, a3 = 0;
            #pragma unroll
            for (int k = 0; k < 16; k++) {
                ulonglong2 w = wp[k];
                ulonglong2 v0 = h0[k], v1 = h1v[k], v2 = h2v[k], v3 = h3v[k];
                a0 = ffma2(w.x, v0.x, a0); a0 = ffma2(w.y, v0.y, a0);
                a1 = ffma2(w.x, v1.x, a1); a1 = ffma2(w.y, v1.y, a1);
                a2 = ffma2(w.x, v2.x, a2); a2 = ffma2(w.y, v2.y, a2);
                a3 = ffma2(w.x, v3.x, a3); a3 = ffma2(w.y, v3.y, a3);
            }
            float2 f0 = unpack2(a0), f1 = unpack2(a1), f2 = unpack2(a2), f3 = unpack2(a3);
            float s0 = f0.x + f0.y, s1 = f1.x + f1.y, s2 = f2.x + f2.y, s3 = f3.x + f3.y;
            s0 += __shfl_xor_sync(0xffffffffu, s0, 16);
            s1 += __shfl_xor_sync(0xffffffffu, s1, 16);
            s2 += __shfl_xor_sync(0xffffffffu, s2, 16);
            s3 += __shfl_xor_sync(0xffffffffu, s3, 16);
            if (kh == 0)
                *(float4*)&gbuf[j1 * 4] = make_float4(s0, s1, s2, s3);
        }

        // ===== wait for h2 of step i-2, then mv2 (dots for step i-1) =====
        if (i > 0) {
            mbar_wait(mb2a, wpar);
            const float* inb = m2 ? &h2bc[p][0][0] : &c1bc[p][0][0];
            const ulonglong2* i0 = (const ulonglong2*)(inb + 0 * HDIM);
            const ulonglong2* i1 = (const ulonglong2*)(inb + 1 * HDIM);
            const ulonglong2* i2 = (const ulonglong2*)(inb + 2 * HDIM);
            const ulonglong2* i3 = (const ulonglong2*)(inb + 3 * HDIM);
            u64 a0 = 0, a1 = 0, a2 = 0, a3 = 0;
            #pragma unroll
            for (int k = 0; k < 32; k++) {
                ulonglong2 v0 = i0[k], v1 = i1[k], v2 = i2[k], v3 = i3[k];
                u64 wa = w2[2 * k], wb = w2[2 * k + 1];
                a0 = ffma2(wa, v0.x, a0); a0 = ffma2(wb, v0.y, a0);
                a1 = ffma2(wa, v1.x, a1); a1 = ffma2(wb, v1.y, a1);
                a2 = ffma2(wa, v2.x, a2); a2 = ffma2(wb, v2.y, a2);
                a3 = ffma2(wa, v3.x, a3); a3 = ffma2(wb, v3.y, a3);
            }
            float2 f0 = unpack2(a0), f1 = unpack2(a1), f2 = unpack2(a2), f3 = unpack2(a3);
            *(float4*)&part2[tid * 4] = make_float4(f0.x + f0.y, f1.x + f1.y,
                                                    f2.x + f2.y, f3.x + f3.y);
        }
        __syncthreads();

        // ===== cell1 (warps 0-3): step i ===== | ===== cell2 (warps 4-7): step i-1 =====
        if (tid < 128) {
            if (i < TSEQ) {
                float xv = xs[cb][i];
                float gi = gbuf[(cu)      * 4 + cb] + fmaf(wih1s[cu],      xv, bias1s[cu]);
                float gf = gbuf[(32 + cu) * 4 + cb] + fmaf(wih1s[32 + cu], xv, bias1s[32 + cu]);
                float gg = gbuf[(64 + cu) * 4 + cb] + fmaf(wih1s[64 + cu], xv, bias1s[64 + cu]);
                float go = gbuf[(96 + cu) * 4 + cb] + fmaf(wih1s[96 + cu], xv, bias1s[96 + cu]);
                c1s = sigm(gf) * c1s + sigm(gi) * tanh_fast(gg);
                float h1n = sigm(go) * tanh_fast(c1s);
                #pragma unroll
                for (int r = 0; r < 4; r++) {
                    st_cluster_f32(&h1bc[pn][cb][slot1], r, h1n);
                    st_cluster_f32(&c1bc[pn][cb][slot1], r, c1s);
                }
                asm volatile("bar.sync 1, 128;" ::: "memory");
                if (tid == 0) {
                    #pragma unroll
                    for (int r = 0; r < 4; r++) mbar_arrive_rank(mb1a, r);
                }
            }
        } else {
            if (i > 0) {
                float gi = part2[(cu2)      * 4 + cb2] + part2[(128 + cu2)      * 4 + cb2] + bias2s[cu2];
                float gf = part2[(32 + cu2) * 4 + cb2] + part2[(128 + 32 + cu2) * 4 + cb2] + bias2s[32 + cu2];
                float gg = part2[(64 + cu2) * 4 + cb2] + part2[(128 + 64 + cu2) * 4 + cb2] + bias2s[64 + cu2];
                float go = part2[(96 + cu2) * 4 + cb2] + part2[(128 + 96 + cu2) * 4 + cb2] + bias2s[96 + cu2];
                c2s = sigm(gf) * c2s + sigm(gi) * tanh_fast(gg);
                float h2n = sigm(go) * tanh_fast(c2s);
                if (i < TSEQ) {
                    #pragma unroll
                    for (int r = 0; r < 4; r++)
                        st_cluster_f32(&h2bc[pn][cb2][slot2], r, h2n);
                }
                g_h2p[(size_t)(i - 1) * (BATCH * HDIM)] = h2n;
            }
            if (i < TSEQ) {
                asm volatile("bar.sync 2, 128;" ::: "memory");
                if (tid == 128) {
                    #pragma unroll
                    for (int r = 0; r < 4; r++) mbar_arrive_rank(mb2a, r);
                }
            }
        }
    }
}

// ---------------------------------------------------------------------------
__global__ void dots_kernel(const float* __restrict__ w_t)
{
    int gid  = blockIdx.x * blockDim.x + threadIdx.x;
    int gw   = gid >> 5;
    int lane = gid & 31;
    if (gw >= TSEQ * BATCH) return;
    float4 h = *(const float4*)(g_h2 + (size_t)gw * HDIM + lane * 4);
    float4 a = *(const float4*)(w_t + lane * 4);
    float4 o = *(const float4*)(w_t + HDIM + lane * 4);
    float dh   = h.x * a.x + h.y * a.y + h.z * a.z + h.w * a.w;
    float dold = h.x * o.x + h.y * o.y + h.z * o.z + h.w * o.w;
    #pragma unroll
    for (int off = 16; off; off >>= 1) {
        dh   += __shfl_down_sync(0xffffffffu, dh, off);
        dold += __shfl_down_sync(0xffffffffu, dold, off);
    }
    if (lane == 0) { g_dh[gw] = dh; g_dold[gw] = dold; }
}

// ---------------------------------------------------------------------------
__global__ void __launch_bounds__(256, 1)
attn_fc_kernel(const float* __restrict__ fcW, const float* __restrict__ fcb,
               float* __restrict__ out)
{
    extern __shared__ float sm[];
    float* sFcT = sm;                       // [128][132]
    float* sPre = sFcT + 128 * RSTRIDE;     // [128][132]
    float* sE   = sPre + 128 * RSTRIDE;     // [33][128]
    float* sHd  = sE + 33 * 128;            // [128]
    float* sFcb = sHd + 128;                // [128]
    float* sRed = sFcb + 128;               // [256]

    const int t    = blockIdx.x;
    const int tid  = threadIdx.x;
    const int lane = tid & 31;
    const int warp = tid >> 5;

    for (int idx = tid; idx < 128 * 128; idx += 256) {
        int c = idx >> 7, h = idx & 127;
        sFcT[h * RSTRIDE + c] = fcW[idx];
    }
    if (tid < 128) {
        sFcb[tid] = fcb[tid];
        sHd[tid]  = g_dh[t * BATCH + tid];
    }
    __syncthreads();

    const int s_min = (t < 32) ? (32 - t) : 0;
    const int nsc   = (33 - s_min) * 128;
    float lmax = -1e30f;
    for (int n = tid; n < nsc; n += 256) {
        int s = s_min + (n >> 7), b = n & 127;
        int idx = t - 33 + s;
        float sc = sHd[b] + (idx >= 0 ? g_dold[idx * BATCH + b] : 0.f);
        sE[s * 128 + b] = sc;
        lmax = fmaxf(lmax, sc);
    }
    sRed[tid] = lmax; __syncthreads();
    for (int off = 128; off; off >>= 1) {
        if (tid < off) sRed[tid] = fmaxf(sRed[tid], sRed[tid + off]);
        __syncthreads();
    }
    float mx = sRed[0];
    __syncthreads();
    float lsum = 0.f;
    for (int n = tid; n < nsc; n += 256) {
        int s = s_min + (n >> 7), b = n & 127;
        float e = __expf(sE[s * 128 + b] - mx);
        sE[s * 128 + b] = e;
        lsum += e;
    }
    sRed[tid] = lsum; __syncthreads();
    for (int off = 128; off; off >>= 1) {
        if (tid < off) sRed[tid] += sRed[tid + off];
        __syncthreads();
    }
    float inv = __fdividef(1.f, sRed[0]);
    __syncthreads();

    const int s_att = (t < 33) ? (33 - t) : 0;
    for (int b = warp; b < 128; b += 8) {
        float4 acc; acc.x = acc.y = acc.z = acc.w = 0.f;
        for (int s = s_att; s < 33; s++) {
            float w  = sE[s * 128 + b];
            float4 v = *(const float4*)(g_h2 + (size_t)(t - 33 + s) * (BATCH * HDIM)
                                              + (size_t)b * HDIM + lane * 4);
            acc.x += w * v.x; acc.y += w * v.y; acc.z += w * v.z; acc.w += w * v.w;
        }
        float4 hc = *(const float4*)(g_h2 + (size_t)t * (BATCH * HDIM)
                                           + (size_t)b * HDIM + lane * 4);
        float4 pre;
        pre.x = hc.x + inv * acc.x; pre.y = hc.y + inv * acc.y;
        pre.z = hc.z + inv * acc.z; pre.w = hc.w + inv * acc.w;
        *(float4*)(sPre + b * RSTRIDE + lane * 4) = pre;
    }
    __syncthreads();

    const int c0 = lane * 4;
    float4 bias = *(const float4*)(sFcb + c0);
    for (int r = 0; r < 4; r++) {
        int b0 = (warp + 8 * r) * 4;
        float4 a0, a1, a2, a3;
        a0.x=a0.y=a0.z=a0.w=0.f; a1=a0; a2=a0; a3=a0;
        const float4* p0 = (const float4*)(sPre + (size_t)(b0 + 0) * RSTRIDE);
        const float4* p1 = (const float4*)(sPre + (size_t)(b0 + 1) * RSTRIDE);
        const float4* p2 = (const float4*)(sPre + (size_t)(b0 + 2) * RSTRIDE);
        const float4* p3 = (const float4*)(sPre + (size_t)(b0 + 3) * RSTRIDE);
        #pragma unroll
        for (int h4 = 0; h4 < 32; h4++) {
            float4 q0 = p0[h4], q1 = p1[h4], q2 = p2[h4], q3 = p3[h4];
            #pragma unroll
            for (int hh = 0; hh < 4; hh++) {
                float4 w = *(const float4*)(sFcT + (h4 * 4 + hh) * RSTRIDE + c0);
                float v0 = (&q0.x)[hh], v1 = (&q1.x)[hh], v2 = (&q2.x)[hh], v3 = (&q3.x)[hh];
                a0.x += v0 * w.x; a0.y += v0 * w.y; a0.z += v0 * w.z; a0.w += v0 * w.w;
                a1.x += v1 * w.x; a1.y += v1 * w.y; a1.z += v1 * w.z; a1.w += v1 * w.w;
                a2.x += v2 * w.x; a2.y += v2 * w.y; a2.z += v2 * w.z; a2.w += v2 * w.w;
                a3.x += v3 * w.x; a3.y += v3 * w.y; a3.z += v3 * w.z; a3.w += v3 * w.w;
            }
        }
        a0.x += bias.x; a0.y += bias.y; a0.z += bias.z; a0.w += bias.w;
        a1.x += bias.x; a1.y += bias.y; a1.z += bias.z; a1.w += bias.w;
        a2.x += bias.x; a2.y += bias.y; a2.z += bias.z; a2.w += bias.w;
        a3.x += bias.x; a3.y += bias.y; a3.z += bias.z; a3.w += bias.w;
        size_t obase = (size_t)t * 128 + c0;
        *(float4*)(out + (size_t)(b0 + 0) * (TSEQ * 128) + obase) = a0;
        *(float4*)(out + (size_t)(b0 + 1) * (TSEQ * 128) + obase) = a1;
        *(float4*)(out + (size_t)(b0 + 2) * (TSEQ * 128) + obase) = a2;
        *(float4*)(out + (size_t)(b0 + 3) * (TSEQ * 128) + obase) = a3;
    }
}

// ---------------------------------------------------------------------------
extern "C" void kernel_launch(void* const* d_in, const int* in_sizes, int n_in,
                              void* d_out, int out_size)
{
    const float* x    = (const float*)d_in[0];
    const float* Wih1 = (const float*)d_in[1];
    const float* Whh1 = (const float*)d_in[2];
    const float* bih1 = (const float*)d_in[3];
    const float* bhh1 = (const float*)d_in[4];
    const float* Wih2 = (const float*)d_in[5];
    const float* Whh2 = (const float*)d_in[6];
    const float* bih2 = (const float*)d_in[7];
    const float* bhh2 = (const float*)d_in[8];
    const float* w_t  = (const float*)d_in[9];
    const float* fcW  = (const float*)d_in[10];
    const float* fcb  = (const float*)d_in[11];
    float* out = (float*)d_out;

    const int smem1 = 128 * W1STRIDE * (int)sizeof(float);   // 67584
    const int smem3 = (2 * 128 * RSTRIDE + 33 * 128 + 128 + 128 + 256) * (int)sizeof(float);

    cudaFuncSetAttribute(lstm_seq_kernel, cudaFuncAttributeMaxDynamicSharedMemorySize, smem1);
    cudaFuncSetAttribute(attn_fc_kernel,  cudaFuncAttributeMaxDynamicSharedMemorySize, smem3);

    lstm_seq_kernel<<<128, 256, smem1>>>(x, Wih1, Whh1, bih1, bhh1,
                                         Wih2, Whh2, bih2, bhh2);
    dots_kernel<<<(TSEQ * BATCH * 32) / 256, 256>>>(w_t);
    attn_fc_kernel<<<TSEQ, 256, smem3>>>(fcW, fcb, out);
}